// round 3
// baseline (speedup 1.0000x reference)
#include <cuda_runtime.h>
#include <math.h>

#define N_B 2
#define T_S 4096
#define D_M 1024
#define H_N 8
#define E_N 4
#define L_W 32
#define TC  128           // T_S / L_W
#define DKV 64

// ---------------- scratch (static __device__, no allocation) ----------------
__device__ float g_lin[(size_t)N_B*T_S*32];          // G logits  (n*t, h*4+e)
__device__ float g_Kb [(size_t)N_B*T_S*512];         // (n*t, h*64+d)
__device__ float g_Vb [(size_t)N_B*T_S*512];
__device__ float g_Qb [(size_t)N_B*T_S*512];
__device__ float g_A  [(size_t)N_B*E_N*T_S];         // (n,e,t)
__device__ float g_gK [(size_t)N_B*E_N*T_S*DKV];     // (n,e,t,d)
__device__ float g_gV [(size_t)N_B*E_N*T_S*DKV];
__device__ float g_nK [(size_t)N_B*E_N*T_S*DKV];
__device__ float g_nV [(size_t)N_B*E_N*T_S*DKV];
__device__ float g_Y  [(size_t)N_B*T_S*512];         // (n*t, h*64+dv)

// ---------------- generic tiled SGEMM -------------------------------------
// C[M,N] = A[M,K] * op(B).  BT=true: B is [N,K] row-major (C=A*B^T).
//                           BT=false: B is [K,N] row-major (C=A*B).
// M % 128 == 0, K % 8 == 0 assumed. N bounds-checked.
template<bool BT>
__global__ void __launch_bounds__(256) sgemm_k(const float* __restrict__ A,
                                               const float* __restrict__ B,
                                               float* __restrict__ C,
                                               int M, int N, int K)
{
    __shared__ float As[8][128];
    __shared__ float Bs[8][128];
    const int tid = threadIdx.x;
    const int m0 = blockIdx.y * 128;
    const int n0 = blockIdx.x * 128;
    const int ty = tid >> 4;            // 0..15
    const int tx = tid & 15;            // 0..15

    float acc[8][8];
#pragma unroll
    for (int i = 0; i < 8; i++)
#pragma unroll
        for (int j = 0; j < 8; j++) acc[i][j] = 0.f;

    const int arow = tid >> 1;          // 0..127
    const int akk  = (tid & 1) * 4;     // 0 or 4

    for (int k0 = 0; k0 < K; k0 += 8) {
        // stage A tile (transposed)
        float4 av = *(const float4*)(A + (size_t)(m0 + arow) * K + k0 + akk);
        As[akk + 0][arow] = av.x;
        As[akk + 1][arow] = av.y;
        As[akk + 2][arow] = av.z;
        As[akk + 3][arow] = av.w;
        // stage B tile
        if (BT) {
            float4 bv = make_float4(0.f, 0.f, 0.f, 0.f);
            if (n0 + arow < N)
                bv = *(const float4*)(B + (size_t)(n0 + arow) * K + k0 + akk);
            Bs[akk + 0][arow] = bv.x;
            Bs[akk + 1][arow] = bv.y;
            Bs[akk + 2][arow] = bv.z;
            Bs[akk + 3][arow] = bv.w;
        } else {
            const int r = tid >> 5;           // 0..7
            const int c = (tid & 31) * 4;     // 0..124
            float4 bv = make_float4(0.f, 0.f, 0.f, 0.f);
            if (n0 + c < N)
                bv = *(const float4*)(B + (size_t)(k0 + r) * N + n0 + c);
            *(float4*)&Bs[r][c] = bv;
        }
        __syncthreads();

#pragma unroll
        for (int kk = 0; kk < 8; kk++) {
            float ra[8], rb[8];
            *(float4*)&ra[0] = *(const float4*)&As[kk][ty * 8 + 0];
            *(float4*)&ra[4] = *(const float4*)&As[kk][ty * 8 + 4];
            *(float4*)&rb[0] = *(const float4*)&Bs[kk][tx * 8 + 0];
            *(float4*)&rb[4] = *(const float4*)&Bs[kk][tx * 8 + 4];
#pragma unroll
            for (int i = 0; i < 8; i++)
#pragma unroll
                for (int j = 0; j < 8; j++)
                    acc[i][j] = fmaf(ra[i], rb[j], acc[i][j]);
        }
        __syncthreads();
    }

#pragma unroll
    for (int i = 0; i < 8; i++) {
        const size_t row = (size_t)(m0 + ty * 8 + i) * N;
#pragma unroll
        for (int j = 0; j < 8; j++) {
            const int col = n0 + tx * 8 + j;
            if (col < N) C[row + col] = acc[i][j];
        }
    }
}

// ---------------- phase 2: sigmoid gate, A, gK, gV -------------------------
__global__ void __launch_bounds__(256) phase2_k(const float* __restrict__ bG)
{
    const int m = blockIdx.x;          // n*T + t
    const int n = m >> 12;
    const int t = m & (T_S - 1);
    const int tid = threadIdx.x;
    __shared__ float Gs[32];

    if (tid < 32) {
        float x = g_lin[(size_t)m * 32 + tid] + bG[tid];
        Gs[tid] = 1.f / (1.f + expf(-x));
    }
    __syncthreads();
    if (tid < E_N) {
        float s = 0.f;
#pragma unroll
        for (int h = 0; h < H_N; h++) s += Gs[h * E_N + tid];
        g_A[(size_t)(n * E_N + tid) * T_S + t] = 1.f - fminf(s, 1.f);
    }
    const int e = tid >> 6;            // 0..3
    const int d = tid & 63;
    float aK = 0.f, aV = 0.f;
#pragma unroll
    for (int h = 0; h < H_N; h++) {
        const float g = Gs[h * E_N + e];
        aK = fmaf(g, g_Kb[(size_t)m * 512 + h * 64 + d], aK);
        aV = fmaf(g, g_Vb[(size_t)m * 512 + h * 64 + d], aV);
    }
    const size_t o = ((size_t)(n * E_N + e) * T_S + t) * DKV + d;
    g_gK[o] = aK;
    g_gV[o] = aV;
}

// ---------------- phase 3: linear scan (128 steps, software pipelined) -----
__global__ void __launch_bounds__(128) scan_k(const float* __restrict__ initK,
                                              const float* __restrict__ initV)
{
    const int b = blockIdx.x;          // n*128 + e*32 + l
    const int n = b >> 7;
    const int r = b & 127;
    const int e = r >> 5;
    const int l = r & 31;
    const int tid = threadIdx.x;
    const int dd = tid & 63;
    const bool isV = tid >= 64;

    float st = (isV ? initV : initK)[(e * L_W + l) * DKV + dd];
    const size_t base = ((size_t)(n * E_N + e) * T_S + l * TC) * DKV + dd;
    const float* g = (isV ? g_gV : g_gK) + base;
    float* o = (isV ? g_nV : g_nK) + base;
    const float* Ap = g_A + (size_t)(n * E_N + e) * T_S + l * TC;

    float a = Ap[0];
    float gv = g[0];
#pragma unroll 4
    for (int c = 0; c < TC; c++) {
        const float an = (c + 1 < TC) ? Ap[c + 1] : 0.f;
        const float gn = (c + 1 < TC) ? g[(size_t)(c + 1) * DKV] : 0.f;
        st = fmaf(a, st, gv);
        o[(size_t)c * DKV] = st;
        a = an;
        gv = gn;
    }
}

// ---------------- phase 4: sliding-window attention ------------------------
#define TT  16
#define WIN (TT + 31)     // 47
#define KPAD 65           // row pad kills stride-64 bank conflicts

__global__ void __launch_bounds__(256) attn_k(const float* __restrict__ initK,
                                              const float* __restrict__ initV)
{
    extern __shared__ float sm[];
    float* sK = sm;                                // [4][WIN][KPAD]
    float* sV = sm + 4 * WIN * KPAD;
    float* qs = sV + 4 * WIN * KPAD;               // [8][64]
    float* ps = qs + 8 * 64;                       // [8][128]

    const int bx = blockIdx.x;
    const int n = bx >> 8;                         // 256 token-tiles per n
    const int t0 = (bx & 255) * TT;
    const int tid = threadIdx.x;

    // stage K/V window: absolute rec index i = t0+1+w, w in [0,WIN)
    for (int idx = tid; idx < 4 * WIN * 16; idx += 256) {
        const int pair = idx >> 4;
        const int f = idx & 15;
        const int e = pair / WIN;
        const int w = pair % WIN;
        const int i = t0 + 1 + w;
        const float *srcK, *srcV;
        if (i < 32) {
            srcK = initK + (e * L_W + i) * DKV;
            srcV = initV + (e * L_W + i) * DKV;
        } else {
            const size_t o = ((size_t)(n * E_N + e) * T_S + (i - 32)) * DKV;
            srcK = g_nK + o;
            srcV = g_nV + o;
        }
        const float4 kv = *(const float4*)(srcK + f * 4);
        const float4 vv = *(const float4*)(srcV + f * 4);
        float* dK = sK + (size_t)(e * WIN + w) * KPAD + f * 4;
        float* dV = sV + (size_t)(e * WIN + w) * KPAD + f * 4;
        dK[0] = kv.x; dK[1] = kv.y; dK[2] = kv.z; dK[3] = kv.w;
        dV[0] = vv.x; dV[1] = vv.y; dV[2] = vv.z; dV[3] = vv.w;
    }
    __syncthreads();

    const int warp = tid >> 5;
    const int lane = tid & 31;

    for (int it = 0; it < 16; it++) {
        const int p = it * 8 + warp;               // (tt, h) pair
        const int tt = p >> 3;
        const int h = p & 7;
        const int t = t0 + tt;

        const float* qg = g_Qb + ((size_t)(n * T_S + t)) * 512 + h * 64;
        qs[warp * 64 + lane] = qg[lane];
        qs[warp * 64 + lane + 32] = qg[lane + 32];
        __syncwarp();

        float s[4];
#pragma unroll
        for (int r = 0; r < 4; r++) {
            const float* kr = sK + (size_t)(r * WIN + tt + lane) * KPAD;
            float acc = 0.f;
#pragma unroll
            for (int d = 0; d < 64; d++)
                acc = fmaf(qs[warp * 64 + d], kr[d], acc);
            s[r] = acc * 0.125f;                   // 1/sqrt(64)
        }
        float mx = fmaxf(fmaxf(s[0], s[1]), fmaxf(s[2], s[3]));
#pragma unroll
        for (int o = 16; o; o >>= 1) mx = fmaxf(mx, __shfl_xor_sync(0xffffffffu, mx, o));
        float sum = 0.f;
#pragma unroll
        for (int r = 0; r < 4; r++) { s[r] = __expf(s[r] - mx); sum += s[r]; }
#pragma unroll
        for (int o = 16; o; o >>= 1) sum += __shfl_xor_sync(0xffffffffu, sum, o);
        const float inv = 1.f / sum;
#pragma unroll
        for (int r = 0; r < 4; r++) ps[warp * 128 + r * 32 + lane] = s[r] * inv;
        __syncwarp();

        float y0 = 0.f, y1 = 0.f;
#pragma unroll 4
        for (int k = 0; k < 128; k++) {
            const int e = k >> 5;
            const int j = k & 31;
            const float pv = ps[warp * 128 + k];
            const float* vr = sV + (size_t)(e * WIN + tt + j) * KPAD;
            y0 = fmaf(pv, vr[lane], y0);
            y1 = fmaf(pv, vr[lane + 32], y1);
        }
        float* yo = g_Y + ((size_t)(n * T_S + t)) * 512 + h * 64;
        yo[lane] = y0;
        yo[lane + 32] = y1;
        __syncwarp();
    }
}

// ---------------- launch ----------------------------------------------------
extern "C" void kernel_launch(void* const* d_in, const int* in_sizes, int n_in,
                              void* d_out, int out_size)
{
    const float* X   = (const float*)d_in[0];
    const float* w_G = (const float*)d_in[1];
    const float* b_G = (const float*)d_in[2];
    const float* w_K = (const float*)d_in[3];
    const float* w_V = (const float*)d_in[4];
    const float* w_Q = (const float*)d_in[5];
    const float* w_O = (const float*)d_in[6];
    const float* iK  = (const float*)d_in[7];
    const float* iV  = (const float*)d_in[8];
    float* out = (float*)d_out;

    float *lin, *Kb, *Vb, *Qb, *Yb;
    cudaGetSymbolAddress((void**)&lin, g_lin);
    cudaGetSymbolAddress((void**)&Kb, g_Kb);
    cudaGetSymbolAddress((void**)&Vb, g_Vb);
    cudaGetSymbolAddress((void**)&Qb, g_Qb);
    cudaGetSymbolAddress((void**)&Yb, g_Y);

    const int M = N_B * T_S;                       // 8192

    dim3 gG(1, M / 128);
    dim3 gP(4, M / 128);
    dim3 gO(8, M / 128);

    sgemm_k<true><<<gG, 256>>>(X, w_G, lin, M, H_N * E_N, D_M);
    sgemm_k<true><<<gP, 256>>>(X, w_K, Kb, M, H_N * DKV, D_M);
    sgemm_k<true><<<gP, 256>>>(X, w_V, Vb, M, H_N * DKV, D_M);
    sgemm_k<true><<<gP, 256>>>(X, w_Q, Qb, M, H_N * DKV, D_M);

    phase2_k<<<M, 256>>>(b_G);
    scan_k<<<N_B * E_N * L_W, 128>>>(iK, iV);

    const int smem = (4 * WIN * KPAD * 2 + 8 * 64 + 8 * 128) * (int)sizeof(float);
    cudaFuncSetAttribute(attn_k, cudaFuncAttributeMaxDynamicSharedMemorySize, smem);
    attn_k<<<N_B * (T_S / TT), 256, smem>>>(iK, iV);

    sgemm_k<false><<<gO, 256>>>(Yb, w_O, out, M, D_M, H_N * DKV);
}

// round 8
// speedup vs baseline: 1.7816x; 1.7816x over previous
#include <cuda_runtime.h>
#include <cuda_bf16.h>
#include <mma.h>
#include <math.h>
#include <type_traits>

using namespace nvcuda;

#define N_B 2
#define T_S 4096
#define D_M 1024
#define H_N 8
#define E_N 4
#define L_W 32
#define TC  128
#define DKV 64

// ---------------- scratch ---------------------------------------------------
__device__ float g_lin[(size_t)N_B*T_S*32];
__device__ float g_Kb [(size_t)N_B*T_S*512];
__device__ float g_Vb [(size_t)N_B*T_S*512];
__device__ float g_Qb [(size_t)N_B*T_S*512];
__device__ float g_A  [(size_t)N_B*E_N*T_S];
__device__ float g_gK [(size_t)N_B*E_N*T_S*DKV];
__device__ float g_gV [(size_t)N_B*E_N*T_S*DKV];
__device__ float g_nK [(size_t)N_B*E_N*T_S*DKV];
__device__ float g_nV [(size_t)N_B*E_N*T_S*DKV];
__device__ float g_Y  [(size_t)N_B*T_S*512];

// bf16 hi/lo split buffers (16B-aligned: accessed through uint4)
__device__ __align__(16) __nv_bfloat16 g_Xhi[(size_t)N_B*T_S*D_M];
__device__ __align__(16) __nv_bfloat16 g_Xlo[(size_t)N_B*T_S*D_M];
__device__ __align__(16) __nv_bfloat16 g_wGhi[32*D_M],  g_wGlo[32*D_M];
__device__ __align__(16) __nv_bfloat16 g_wKhi[512*D_M], g_wKlo[512*D_M];
__device__ __align__(16) __nv_bfloat16 g_wVhi[512*D_M], g_wVlo[512*D_M];
__device__ __align__(16) __nv_bfloat16 g_wQhi[512*D_M], g_wQlo[512*D_M];
__device__ __align__(16) __nv_bfloat16 g_wOhi[512*D_M], g_wOlo[512*D_M];
__device__ __align__(16) __nv_bfloat16 g_Yhi[(size_t)N_B*T_S*512];
__device__ __align__(16) __nv_bfloat16 g_Ylo[(size_t)N_B*T_S*512];

// ---------------- fp32 -> (hi,lo) bf16 split --------------------------------
__global__ void __launch_bounds__(256) split_k(const float* __restrict__ x,
                                               __nv_bfloat16* __restrict__ hi,
                                               __nv_bfloat16* __restrict__ lo,
                                               int n4)
{
    const int i = blockIdx.x * 256 + threadIdx.x;
    if (i >= n4) return;
    const float4 v = ((const float4*)x)[i];
    __nv_bfloat16 h0 = __float2bfloat16(v.x);
    __nv_bfloat16 h1 = __float2bfloat16(v.y);
    __nv_bfloat16 h2 = __float2bfloat16(v.z);
    __nv_bfloat16 h3 = __float2bfloat16(v.w);
    __nv_bfloat16 l0 = __float2bfloat16(v.x - __bfloat162float(h0));
    __nv_bfloat16 l1 = __float2bfloat16(v.y - __bfloat162float(h1));
    __nv_bfloat16 l2 = __float2bfloat16(v.z - __bfloat162float(h2));
    __nv_bfloat16 l3 = __float2bfloat16(v.w - __bfloat162float(h3));
    ((__nv_bfloat162*)hi)[i*2+0] = __nv_bfloat162(h0, h1);
    ((__nv_bfloat162*)hi)[i*2+1] = __nv_bfloat162(h2, h3);
    ((__nv_bfloat162*)lo)[i*2+0] = __nv_bfloat162(l0, l1);
    ((__nv_bfloat162*)lo)[i*2+1] = __nv_bfloat162(l2, l3);
}

// ---------------- bf16 split-precision GEMM (tensor cores) ------------------
// C[M,N](fp32) = (Ahi+Alo)[M,K] * op(Bhi+Blo), dropping Alo*Blo.
// BT=true:  B is [N,K] row-major (C = A * B^T)
// BT=false: B is [K,N] row-major (C = A * B)
// M%128==0, K%32==0. N bounds handled at fragment granularity.
#define KT 32
#define LDA 40
#define LDB2 136

template<bool BT>
__global__ void __launch_bounds__(256) gemm_bf16_k(
    const __nv_bfloat16* __restrict__ Ahi, const __nv_bfloat16* __restrict__ Alo,
    const __nv_bfloat16* __restrict__ Bhi, const __nv_bfloat16* __restrict__ Blo,
    float* __restrict__ C, int M, int N, int K)
{
    __shared__ __align__(16) __nv_bfloat16 smem[2*128*LDA + 2*128*LDA];
    __nv_bfloat16* sAh = smem;                 // [128][LDA]
    __nv_bfloat16* sAl = sAh + 128*LDA;
    __nv_bfloat16* sBh = sAl + 128*LDA;        // BT: [128][LDA] ; !BT: [KT][LDB2]
    __nv_bfloat16* sBl = sBh + (BT ? 128*LDA : KT*LDB2);

    const int tid = threadIdx.x;
    const int m0 = blockIdx.y * 128;
    const int n0 = blockIdx.x * 128;
    const int warp = tid >> 5;
    const int wm = warp >> 1;          // 0..3  (32-row slab)
    const int wn = warp & 1;           // 0..1  (64-col slab)

    wmma::fragment<wmma::matrix_a, 16,16,16, __nv_bfloat16, wmma::row_major> ah[2], al[2];
    using BLayout = typename std::conditional<BT, wmma::col_major, wmma::row_major>::type;
    wmma::fragment<wmma::matrix_b, 16,16,16, __nv_bfloat16, BLayout> bh, bl;
    wmma::fragment<wmma::accumulator, 16,16,16, float> c[2][4];
#pragma unroll
    for (int im = 0; im < 2; im++)
#pragma unroll
        for (int jn = 0; jn < 4; jn++) wmma::fill_fragment(c[im][jn], 0.f);

    for (int k0 = 0; k0 < K; k0 += KT) {
        // stage A (hi & lo): 128 rows x KT cols, uint4 = 8 bf16
#pragma unroll
        for (int i = tid; i < 128*4; i += 256) {
            const int row = i >> 2;
            const int cc = (i & 3) * 8;
            const size_t go = (size_t)(m0 + row) * K + k0 + cc;
            *(uint4*)(sAh + row*LDA + cc) = *(const uint4*)(Ahi + go);
            *(uint4*)(sAl + row*LDA + cc) = *(const uint4*)(Alo + go);
        }
        if (BT) {
            // B [N,K]: 128 n-rows x KT cols
#pragma unroll
            for (int i = tid; i < 128*4; i += 256) {
                const int row = i >> 2;
                const int cc = (i & 3) * 8;
                uint4 vh = make_uint4(0,0,0,0), vl = make_uint4(0,0,0,0);
                if (n0 + row < N) {
                    const size_t go = (size_t)(n0 + row) * K + k0 + cc;
                    vh = *(const uint4*)(Bhi + go);
                    vl = *(const uint4*)(Blo + go);
                }
                *(uint4*)(sBh + row*LDA + cc) = vh;
                *(uint4*)(sBl + row*LDA + cc) = vl;
            }
        } else {
            // B [K,N]: KT k-rows x 128 n-cols
#pragma unroll
            for (int i = tid; i < KT*16; i += 256) {
                const int row = i >> 4;
                const int cc = (i & 15) * 8;
                uint4 vh = make_uint4(0,0,0,0), vl = make_uint4(0,0,0,0);
                if (n0 + cc < N) {
                    const size_t go = (size_t)(k0 + row) * N + n0 + cc;
                    vh = *(const uint4*)(Bhi + go);
                    vl = *(const uint4*)(Blo + go);
                }
                *(uint4*)(sBh + row*LDB2 + cc) = vh;
                *(uint4*)(sBl + row*LDB2 + cc) = vl;
            }
        }
        __syncthreads();

#pragma unroll
        for (int kk = 0; kk < KT/16; kk++) {
#pragma unroll
            for (int im = 0; im < 2; im++) {
                const __nv_bfloat16* ap = sAh + (wm*32 + im*16)*LDA + kk*16;
                const __nv_bfloat16* alp = sAl + (wm*32 + im*16)*LDA + kk*16;
                wmma::load_matrix_sync(ah[im], ap, LDA);
                wmma::load_matrix_sync(al[im], alp, LDA);
            }
#pragma unroll
            for (int jn = 0; jn < 4; jn++) {
                if (BT) {
                    const __nv_bfloat16* bp = sBh + (wn*64 + jn*16)*LDA + kk*16;
                    const __nv_bfloat16* blp = sBl + (wn*64 + jn*16)*LDA + kk*16;
                    wmma::load_matrix_sync(bh, bp, LDA);
                    wmma::load_matrix_sync(bl, blp, LDA);
                } else {
                    const __nv_bfloat16* bp = sBh + (kk*16)*LDB2 + wn*64 + jn*16;
                    const __nv_bfloat16* blp = sBl + (kk*16)*LDB2 + wn*64 + jn*16;
                    wmma::load_matrix_sync(bh, bp, LDB2);
                    wmma::load_matrix_sync(bl, blp, LDB2);
                }
#pragma unroll
                for (int im = 0; im < 2; im++) {
                    wmma::mma_sync(c[im][jn], ah[im], bh, c[im][jn]);
                    wmma::mma_sync(c[im][jn], ah[im], bl, c[im][jn]);
                    wmma::mma_sync(c[im][jn], al[im], bh, c[im][jn]);
                }
            }
        }
        __syncthreads();
    }

#pragma unroll
    for (int im = 0; im < 2; im++)
#pragma unroll
        for (int jn = 0; jn < 4; jn++) {
            const int fn = n0 + wn*64 + jn*16;
            if (fn < N)
                wmma::store_matrix_sync(C + (size_t)(m0 + wm*32 + im*16)*N + fn,
                                        c[im][jn], N, wmma::mem_row_major);
        }
}

// ---------------- phase 2: sigmoid gate, A, gK, gV -------------------------
__global__ void __launch_bounds__(256) phase2_k(const float* __restrict__ bG)
{
    const int m = blockIdx.x;
    const int n = m >> 12;
    const int t = m & (T_S - 1);
    const int tid = threadIdx.x;
    __shared__ float Gs[32];

    if (tid < 32) {
        float x = g_lin[(size_t)m * 32 + tid] + bG[tid];
        Gs[tid] = 1.f / (1.f + expf(-x));
    }
    __syncthreads();
    if (tid < E_N) {
        float s = 0.f;
#pragma unroll
        for (int h = 0; h < H_N; h++) s += Gs[h * E_N + tid];
        g_A[(size_t)(n * E_N + tid) * T_S + t] = 1.f - fminf(s, 1.f);
    }
    const int e = tid >> 6;
    const int d = tid & 63;
    float aK = 0.f, aV = 0.f;
#pragma unroll
    for (int h = 0; h < H_N; h++) {
        const float g = Gs[h * E_N + e];
        aK = fmaf(g, g_Kb[(size_t)m * 512 + h * 64 + d], aK);
        aV = fmaf(g, g_Vb[(size_t)m * 512 + h * 64 + d], aV);
    }
    const size_t o = ((size_t)(n * E_N + e) * T_S + t) * DKV + d;
    g_gK[o] = aK;
    g_gV[o] = aV;
}

// ---------------- phase 3: linear scan --------------------------------------
__global__ void __launch_bounds__(128) scan_k(const float* __restrict__ initK,
                                              const float* __restrict__ initV)
{
    const int b = blockIdx.x;
    const int n = b >> 7;
    const int r = b & 127;
    const int e = r >> 5;
    const int l = r & 31;
    const int tid = threadIdx.x;
    const int dd = tid & 63;
    const bool isV = tid >= 64;

    float st = (isV ? initV : initK)[(e * L_W + l) * DKV + dd];
    const size_t base = ((size_t)(n * E_N + e) * T_S + l * TC) * DKV + dd;
    const float* g = (isV ? g_gV : g_gK) + base;
    float* o = (isV ? g_nV : g_nK) + base;
    const float* Ap = g_A + (size_t)(n * E_N + e) * T_S + l * TC;

    float a = Ap[0];
    float gv = g[0];
#pragma unroll 4
    for (int c = 0; c < TC; c++) {
        const float an = (c + 1 < TC) ? Ap[c + 1] : 0.f;
        const float gn = (c + 1 < TC) ? g[(size_t)(c + 1) * DKV] : 0.f;
        st = fmaf(a, st, gv);
        o[(size_t)c * DKV] = st;
        a = an;
        gv = gn;
    }
}

// ---------------- phase 4: sliding-window attention ------------------------
#define TT  16
#define WIN (TT + 31)
#define KPAD 65

__global__ void __launch_bounds__(256) attn_k(const float* __restrict__ initK,
                                              const float* __restrict__ initV)
{
    extern __shared__ float sm[];
    float* sK = sm;
    float* sV = sm + 4 * WIN * KPAD;
    float* qs = sV + 4 * WIN * KPAD;
    float* ps = qs + 8 * 64;

    const int bx = blockIdx.x;
    const int n = bx >> 8;
    const int t0 = (bx & 255) * TT;
    const int tid = threadIdx.x;

    for (int idx = tid; idx < 4 * WIN * 16; idx += 256) {
        const int pair = idx >> 4;
        const int f = idx & 15;
        const int e = pair / WIN;
        const int w = pair % WIN;
        const int i = t0 + 1 + w;
        const float *srcK, *srcV;
        if (i < 32) {
            srcK = initK + (e * L_W + i) * DKV;
            srcV = initV + (e * L_W + i) * DKV;
        } else {
            const size_t o = ((size_t)(n * E_N + e) * T_S + (i - 32)) * DKV;
            srcK = g_nK + o;
            srcV = g_nV + o;
        }
        const float4 kv = *(const float4*)(srcK + f * 4);
        const float4 vv = *(const float4*)(srcV + f * 4);
        float* dK = sK + (size_t)(e * WIN + w) * KPAD + f * 4;
        float* dV = sV + (size_t)(e * WIN + w) * KPAD + f * 4;
        dK[0] = kv.x; dK[1] = kv.y; dK[2] = kv.z; dK[3] = kv.w;
        dV[0] = vv.x; dV[1] = vv.y; dV[2] = vv.z; dV[3] = vv.w;
    }
    __syncthreads();

    const int warp = tid >> 5;
    const int lane = tid & 31;

    for (int it = 0; it < 16; it++) {
        const int p = it * 8 + warp;
        const int tt = p >> 3;
        const int h = p & 7;
        const int t = t0 + tt;

        const float* qg = g_Qb + ((size_t)(n * T_S + t)) * 512 + h * 64;
        qs[warp * 64 + lane] = qg[lane];
        qs[warp * 64 + lane + 32] = qg[lane + 32];
        __syncwarp();

        float s[4];
#pragma unroll
        for (int r = 0; r < 4; r++) {
            const float* kr = sK + (size_t)(r * WIN + tt + lane) * KPAD;
            float acc = 0.f;
#pragma unroll
            for (int d = 0; d < 64; d++)
                acc = fmaf(qs[warp * 64 + d], kr[d], acc);
            s[r] = acc * 0.125f;
        }
        float mx = fmaxf(fmaxf(s[0], s[1]), fmaxf(s[2], s[3]));
#pragma unroll
        for (int o = 16; o; o >>= 1) mx = fmaxf(mx, __shfl_xor_sync(0xffffffffu, mx, o));
        float sum = 0.f;
#pragma unroll
        for (int r = 0; r < 4; r++) { s[r] = __expf(s[r] - mx); sum += s[r]; }
#pragma unroll
        for (int o = 16; o; o >>= 1) sum += __shfl_xor_sync(0xffffffffu, sum, o);
        const float inv = 1.f / sum;
#pragma unroll
        for (int r = 0; r < 4; r++) ps[warp * 128 + r * 32 + lane] = s[r] * inv;
        __syncwarp();

        float y0 = 0.f, y1 = 0.f;
#pragma unroll 4
        for (int k = 0; k < 128; k++) {
            const int e = k >> 5;
            const int j = k & 31;
            const float pv = ps[warp * 128 + k];
            const float* vr = sV + (size_t)(e * WIN + tt + j) * KPAD;
            y0 = fmaf(pv, vr[lane], y0);
            y1 = fmaf(pv, vr[lane + 32], y1);
        }
        float* yo = g_Y + ((size_t)(n * T_S + t)) * 512 + h * 64;
        yo[lane] = y0;
        yo[lane + 32] = y1;
        __syncwarp();
    }
}

// ---------------- launch ----------------------------------------------------
extern "C" void kernel_launch(void* const* d_in, const int* in_sizes, int n_in,
                              void* d_out, int out_size)
{
    const float* X   = (const float*)d_in[0];
    const float* w_G = (const float*)d_in[1];
    const float* b_G = (const float*)d_in[2];
    const float* w_K = (const float*)d_in[3];
    const float* w_V = (const float*)d_in[4];
    const float* w_Q = (const float*)d_in[5];
    const float* w_O = (const float*)d_in[6];
    const float* iK  = (const float*)d_in[7];
    const float* iV  = (const float*)d_in[8];
    float* out = (float*)d_out;

    float *lin, *Kb, *Vb, *Qb, *Yb;
    cudaGetSymbolAddress((void**)&lin, g_lin);
    cudaGetSymbolAddress((void**)&Kb, g_Kb);
    cudaGetSymbolAddress((void**)&Vb, g_Vb);
    cudaGetSymbolAddress((void**)&Qb, g_Qb);
    cudaGetSymbolAddress((void**)&Yb, g_Y);

    __nv_bfloat16 *Xhi, *Xlo, *wGhi, *wGlo, *wKhi, *wKlo, *wVhi, *wVlo;
    __nv_bfloat16 *wQhi, *wQlo, *wOhi, *wOlo, *Yhi, *Ylo;
    cudaGetSymbolAddress((void**)&Xhi, g_Xhi);
    cudaGetSymbolAddress((void**)&Xlo, g_Xlo);
    cudaGetSymbolAddress((void**)&wGhi, g_wGhi);
    cudaGetSymbolAddress((void**)&wGlo, g_wGlo);
    cudaGetSymbolAddress((void**)&wKhi, g_wKhi);
    cudaGetSymbolAddress((void**)&wKlo, g_wKlo);
    cudaGetSymbolAddress((void**)&wVhi, g_wVhi);
    cudaGetSymbolAddress((void**)&wVlo, g_wVlo);
    cudaGetSymbolAddress((void**)&wQhi, g_wQhi);
    cudaGetSymbolAddress((void**)&wQlo, g_wQlo);
    cudaGetSymbolAddress((void**)&wOhi, g_wOhi);
    cudaGetSymbolAddress((void**)&wOlo, g_wOlo);
    cudaGetSymbolAddress((void**)&Yhi, g_Yhi);
    cudaGetSymbolAddress((void**)&Ylo, g_Ylo);

    const int M = N_B * T_S;                       // 8192

    // splits
    {
        int n4 = M * D_M / 4;
        split_k<<<(n4 + 255) / 256, 256>>>(X, Xhi, Xlo, n4);
        n4 = 32 * D_M / 4;
        split_k<<<(n4 + 255) / 256, 256>>>(w_G, wGhi, wGlo, n4);
        n4 = 512 * D_M / 4;
        split_k<<<(n4 + 255) / 256, 256>>>(w_K, wKhi, wKlo, n4);
        split_k<<<(n4 + 255) / 256, 256>>>(w_V, wVhi, wVlo, n4);
        split_k<<<(n4 + 255) / 256, 256>>>(w_Q, wQhi, wQlo, n4);
        split_k<<<(n4 + 255) / 256, 256>>>(w_O, wOhi, wOlo, n4);
    }

    // projection GEMMs (C = X * W^T), tensor cores
    gemm_bf16_k<true><<<dim3(1, M/128), 256>>>(Xhi, Xlo, wGhi, wGlo, lin, M, 32,  D_M);
    gemm_bf16_k<true><<<dim3(4, M/128), 256>>>(Xhi, Xlo, wKhi, wKlo, Kb,  M, 512, D_M);
    gemm_bf16_k<true><<<dim3(4, M/128), 256>>>(Xhi, Xlo, wVhi, wVlo, Vb,  M, 512, D_M);
    gemm_bf16_k<true><<<dim3(4, M/128), 256>>>(Xhi, Xlo, wQhi, wQlo, Qb,  M, 512, D_M);

    phase2_k<<<M, 256>>>(b_G);
    scan_k<<<N_B * E_N * L_W, 128>>>(iK, iV);

    const int smem = (4 * WIN * KPAD * 2 + 8 * 64 + 8 * 128) * (int)sizeof(float);
    cudaFuncSetAttribute(attn_k, cudaFuncAttributeMaxDynamicSharedMemorySize, smem);
    attn_k<<<N_B * (T_S / TT), 256, smem>>>(iK, iV);

    // split Y, output GEMM (C = Y * w_O)
    {
        const int n4 = M * 512 / 4;
        split_k<<<(n4 + 255) / 256, 256>>>(Yb, Yhi, Ylo, n4);
    }
    gemm_bf16_k<false><<<dim3(8, M/128), 256>>>(Yhi, Ylo, wOhi, wOlo, out, M, D_M, 512);
}